// round 16
// baseline (speedup 1.0000x reference)
#include <cuda_runtime.h>
#include <math.h>
#include <stdint.h>

#define N_IMG 4608
#define N_TXT 128
#define DIM   4096
#define NB    4096
#define NTH   1024
#define NBLK  148
#define CE    5          // elements per thread in topp block (ceil(4608/1024))

#define TOTF4   (N_IMG * (DIM / 4))   // 4718592 float4 elements
#define A_END   524288                // rows [0,512)    copied in phase A
#define B_END   1048576               // rows [512,1024) copied in phase B
#define RSPLIT  1280                  // rows [1024,1280) stored fused in C
#define D_BEG   (RSPLIT * (DIM / 4))  // rows [1280,4608) copied in phase D

// ---- scratch (no allocations allowed) ----
__device__ float g_v[DIM];
__device__ float g_invn[N_TXT];
__device__ float g_sim[N_IMG];
__device__ unsigned char g_keep[N_IMG];
__device__ unsigned int g_cnt = 0;
__device__ volatile unsigned int g_gen = 0;

// All NBLK blocks resident (1 CTA/SM, grid == 148 <= SM count): spin barrier
// is safe. Counting barrier with generation; g_cnt self-resets, g_gen grows
// monotonically across graph replays (each launch reads its start gen).
__device__ __forceinline__ void grid_bar(unsigned int& gen) {
    __syncthreads();
    if (threadIdx.x == 0) {
        __threadfence();
        unsigned int arrived = atomicAdd(&g_cnt, 1);
        if (arrived == NBLK - 1) {
            g_cnt = 0;
            __threadfence();
            g_gen = gen + 1;
        } else {
            while (g_gen == gen) { }
        }
        __threadfence();
    }
    __syncthreads();
    gen++;
}

// 4-deep-ILP copy of float4 range [lo,hi): 4 independent loads, then 4 stores.
__device__ __forceinline__ void copy_range(const float4* __restrict__ src,
                                           float4* __restrict__ dst,
                                           int lo, int hi, int tg, int nth) {
    for (int i = lo + tg; i < hi; i += 4 * nth) {
        int i1 = i + nth, i2 = i + 2 * nth, i3 = i + 3 * nth;
        float4 a0 = src[i];
        float4 a1, a2, a3;
        if (i1 < hi) a1 = src[i1];
        if (i2 < hi) a2 = src[i2];
        if (i3 < hi) a3 = src[i3];
        dst[i] = a0;
        if (i1 < hi) dst[i1] = a1;
        if (i2 < hi) dst[i2] = a2;
        if (i3 < hi) dst[i3] = a3;
    }
}

// ---------------------------------------------------------------------------
// Mega-kernel. Shared layout (bytes), used only by block 0's top-p phase:
//   pval : [0,     18432)   lst : [18432, 36864)
//   P    : [36864, 53248)   S   : [53248, 86016)
//   daux : [86016, 86272)   iaux: [86272, 86400)
//   red  : [86400, 86656)   ictl: [86656, 86664)
// ---------------------------------------------------------------------------
#define SMEM3 86720

__global__ void __launch_bounds__(NTH, 1)
k_mega(const float* __restrict__ lf,
       const float* __restrict__ emb,
       const unsigned char* __restrict__ maskb,
       const float* __restrict__ gnoise,
       float* __restrict__ out) {
    extern __shared__ unsigned char sraw[];
    float*  pval = (float*)(sraw);
    int*    lst  = (int*)(sraw + 18432);
    int*    P    = (int*)(sraw + 36864);
    double* S    = (double*)(sraw + 53248);
    double* daux = (double*)(sraw + 86016);
    int*    iaux = (int*)(sraw + 86272);
    float*  red  = (float*)(sraw + 86400);
    int*    ictl = (int*)(sraw + 86656);

    const int b    = blockIdx.x;
    const int tid  = threadIdx.x;
    const int lane = tid & 31;
    const int w    = tid >> 5;

    unsigned int gen = g_gen;

    const float4* srcf4 = (const float4*)lf;
    float4* dstf4 = (float4*)out;

    float val[CE];
    float pv[CE];
    float gn[CE];
    const int s0 = tid * CE;
    const int nmine = min(CE, max(0, N_IMG - s0));

    // ========== A: textnorm (blocks 0..3) || ILP-copy rows [0,512) =========
    if (b < 4) {
        int t = b * 32 + w;                       // 0..127
        const float4* row = (const float4*)(emb + (size_t)t * DIM);
        float ss = 0.f;
#pragma unroll 8
        for (int k = 0; k < 32; k++) {
            float4 a = row[k * 32 + lane];
            ss += a.x * a.x + a.y * a.y + a.z * a.z + a.w * a.w;
        }
        for (int o = 16; o; o >>= 1) ss += __shfl_xor_sync(0xffffffffu, ss, o);
        // bool-layout probe: u8 layout has nonzero bytes at j%4!=0 in first
        // 128 bytes; i32 layout has flags only in byte 0 of each word.
        unsigned word = ((const unsigned*)maskb)[lane];
        bool isU8 = __ballot_sync(0xffffffffu, (word & 0xFFFFFF00u) != 0) != 0;
        if (lane == 0) {
            bool mv = isU8 ? (maskb[t] != 0) : (((const int*)maskb)[t] != 0);
            float n = fmaxf(sqrtf(ss), 1e-8f);
            g_invn[t] = mv ? (1.f / n) : 0.f;
        }
    } else {
        copy_range(srcf4, dstf4, 0, A_END, (b - 4) * NTH + tid, 144 * NTH);
    }
    grid_bar(gen);

    // ========== B: buildv (1..4) || blk0 prologue || copy rows [512,1024) ==
    if (b >= 1 && b <= 4) {
        int d = (b - 1) * NTH + tid;              // 0..4095
        float acc = 0.f;
#pragma unroll 8
        for (int t = 0; t < N_TXT; t++)
            acc = fmaf(emb[(size_t)t * DIM + d], g_invn[t], acc);
        g_v[d] = acc;
    } else if (b == 0) {
        for (int bb = tid; bb < NB; bb += NTH) { P[bb] = 0; S[bb] = 0.0; }
        if (tid == 0) ictl[0] = NB;
#pragma unroll
        for (int j = 0; j < CE; j++)
            if (j < nmine) gn[j] = gnoise[s0 + j];
    } else {
        copy_range(srcf4, dstf4, A_END, B_END, (b - 5) * NTH + tid, 143 * NTH);
    }
    grid_bar(gen);

    // ========== C: sims (warp-per-row); rows [1024,RSPLIT) also store ======
    {
        int r = b * 32 + w;                       // 0..4735
        if (r < N_IMG) {
            const float4* row = (const float4*)(lf + (size_t)r * DIM);
            float4* orow = (float4*)(out + (size_t)r * DIM);
            const float4* v4  = (const float4*)g_v;
            bool do_store = (r >= 1024 && r < RSPLIT);
            float dot = 0.f, ss = 0.f;
#pragma unroll 8
            for (int k = 0; k < 32; k++) {
                float4 a = row[k * 32 + lane];
                float4 vv = v4[k * 32 + lane];
                dot += a.x * vv.x + a.y * vv.y + a.z * vv.z + a.w * vv.w;
                ss  += a.x * a.x + a.y * a.y + a.z * a.z + a.w * a.w;
                if (do_store) orow[k * 32 + lane] = a;
            }
            for (int o = 16; o; o >>= 1) {
                dot += __shfl_xor_sync(0xffffffffu, dot, o);
                ss  += __shfl_xor_sync(0xffffffffu, ss, o);
            }
            if (lane == 0) {
                float n = fmaxf(sqrtf(ss), 1e-8f);
                g_sim[r] = dot / n;
            }
        }
    }
    grid_bar(gen);

    // ========== D: block 0 top-p || blocks 1..147 copy rows [RSPLIT,4608) ==
    if (b != 0) {
        copy_range(srcf4, dstf4, D_BEG, TOTF4, (b - 1) * NTH + tid, 147 * NTH);
    } else {
        // ---- pass 1: t = 2*sim, max -> m1 ----
        float lm = -INFINITY;
#pragma unroll
        for (int j = 0; j < CE; j++) {
            if (j < nmine) {
                float t = 2.f * g_sim[s0 + j];
                val[j] = t;
                lm = fmaxf(lm, t);
            }
        }
        for (int o = 16; o; o >>= 1) lm = fmaxf(lm, __shfl_xor_sync(0xffffffffu, lm, o));
        if (lane == 0) red[w] = lm;
        __syncthreads();
        if (tid < 32) {
            float x = red[tid];
            for (int o = 16; o; o >>= 1) x = fmaxf(x, __shfl_xor_sync(0xffffffffu, x, o));
            if (tid == 0) red[0] = x;
        }
        __syncthreads();
        float m1 = red[0];
        __syncthreads();

        // ---- pass 2: e = exp(t - m1), sum -> Z1 ----
        float lsum = 0.f;
#pragma unroll
        for (int j = 0; j < CE; j++) {
            if (j < nmine) {
                float e = expf(val[j] - m1);
                val[j] = e;
                lsum += e;
            }
        }
        for (int o = 16; o; o >>= 1) lsum += __shfl_xor_sync(0xffffffffu, lsum, o);
        if (lane == 0) red[w] = lsum;
        __syncthreads();
        if (tid < 32) {
            float x = red[tid];
            for (int o = 16; o; o >>= 1) x += __shfl_xor_sync(0xffffffffu, x, o);
            if (tid == 0) red[0] = x;
        }
        __syncthreads();
        float Z1 = red[0];
        float r1 = 1.f / Z1;
        __syncthreads();

        // ---- pass 3: z = e/Z1 + g, max -> m2 ----
        float lm2 = -INFINITY;
#pragma unroll
        for (int j = 0; j < CE; j++) {
            if (j < nmine) {
                float z = val[j] * r1 + gn[j];
                val[j] = z;
                lm2 = fmaxf(lm2, z);
            }
        }
        for (int o = 16; o; o >>= 1) lm2 = fmaxf(lm2, __shfl_xor_sync(0xffffffffu, lm2, o));
        if (lane == 0) red[w] = lm2;
        __syncthreads();
        if (tid < 32) {
            float x = red[tid];
            for (int o = 16; o; o >>= 1) x = fmaxf(x, __shfl_xor_sync(0xffffffffu, x, o));
            if (tid == 0) red[0] = x;
        }
        __syncthreads();
        float m2 = red[0];
        __syncthreads();

        // ---- pass 4: e2 = exp(z - m2); sum + min/max in one reduction ----
        float ls2 = 0.f, emin = INFINITY, emax = -INFINITY;
#pragma unroll
        for (int j = 0; j < CE; j++) {
            if (j < nmine) {
                float e = expf(val[j] - m2);
                val[j] = e;
                ls2 += e;
                emin = fminf(emin, e);
                emax = fmaxf(emax, e);
            }
        }
        for (int o = 16; o; o >>= 1) {
            ls2  += __shfl_xor_sync(0xffffffffu, ls2, o);
            emin  = fminf(emin, __shfl_xor_sync(0xffffffffu, emin, o));
            emax  = fmaxf(emax, __shfl_xor_sync(0xffffffffu, emax, o));
        }
        if (lane == 0) { red[w] = ls2; red[32 + w] = emin; daux[w] = (double)emax; }
        __syncthreads();
        if (tid < 32) {
            float a = red[tid];
            float bb = red[32 + tid];
            float c = (float)daux[tid];
            for (int o = 16; o; o >>= 1) {
                a += __shfl_xor_sync(0xffffffffu, a, o);
                bb = fminf(bb, __shfl_xor_sync(0xffffffffu, bb, o));
                c  = fmaxf(c, __shfl_xor_sync(0xffffffffu, c, o));
            }
            if (tid == 0) { red[0] = a; red[1] = bb; red[2] = c; }
        }
        __syncthreads();
        float Z2 = red[0];
        float pmin = red[1] / Z2;   // p=f32(e2/Z2) monotone in e2 -> exact
        float pmax = red[2] / Z2;
        float scale = (float)(NB - 1) / fmaxf(pmax - pmin, 1e-30f);
        __syncthreads();

#define BUCKET(p) min(max((int)((pmax - (p)) * scale), 0), NB - 1)

        // ---- p = e2/Z2 (exact div); count + double sum per bucket ----
#pragma unroll
        for (int j = 0; j < CE; j++) {
            if (j < nmine) {
                float p = val[j] / Z2;
                pv[j] = p;
                int bd = BUCKET(p);
                atomicAdd(&P[bd], 1);
                atomicAdd(&S[bd], (double)p);
            }
        }
        __syncthreads();

        // ---- fused scans: P -> excl starts, S -> incl double prefix ----
        const int CB = NB / NTH;  // 4
        int base = tid * CB;
        int run = 0; double drun = 0.0;
#pragma unroll
        for (int j = 0; j < CB; j++) {
            int t = P[base + j];
            P[base + j] = run;
            run += t;
            drun += S[base + j];
            S[base + j] = drun;
        }
        int iv = run; double dvv = drun;
        for (int o = 1; o < 32; o <<= 1) {
            int ti = __shfl_up_sync(0xffffffffu, iv, o);
            double td = __shfl_up_sync(0xffffffffu, dvv, o);
            if (lane >= o) { iv += ti; dvv += td; }
        }
        if (lane == 31) { iaux[w] = iv; daux[w] = dvv; }
        __syncthreads();
        if (tid < 32) {
            int x = iaux[tid]; double y = daux[tid];
            for (int o = 1; o < 32; o <<= 1) {
                int ti = __shfl_up_sync(0xffffffffu, x, o);
                double td = __shfl_up_sync(0xffffffffu, y, o);
                if (tid >= o) { x += ti; y += td; }
            }
            iaux[tid] = x; daux[tid] = y;
        }
        __syncthreads();
        int iexcl = (iv - run) + (w ? iaux[w - 1] : 0);
        double dexcl = (dvv - drun) + (w ? daux[w - 1] : 0.0);
        if (iexcl) {
#pragma unroll
            for (int j = 0; j < CB; j++) P[base + j] += iexcl;
        }
        if (dexcl != 0.0) {
#pragma unroll
            for (int j = 0; j < CB; j++) S[base + j] += dexcl;
        }
        __syncthreads();

        // ---- scatter (p, id) by bucket; P becomes bucket ends ----
#pragma unroll
        for (int j = 0; j < CE; j++) {
            if (j < nmine) {
                int bd = BUCKET(pv[j]);
                int pos = atomicAdd(&P[bd], 1);
                lst[pos] = s0 + j;
                pval[pos] = pv[j];
            }
        }
        __syncthreads();

        const double TOPPD = (double)0.9f;  // jax promotes 0.9 -> f32

        // ---- find crossing bucket b*: S[b*] > 0.9 >= S[b*-1] ----
#pragma unroll
        for (int j = 0; j < CB; j++) {
            int bb = base + j;
            double incl = S[bb];
            double prev = bb ? S[bb - 1] : 0.0;
            if (incl > TOPPD && prev <= TOPPD) atomicMin(&ictl[0], bb);
        }
        __syncthreads();
        int bstar = ictl[0];

        // ---- warp 0: resolve crossing bucket exactly -> count, k ----
        if (w == 0) {
            int count;
            if (bstar >= NB) {
                count = N_IMG;
            } else {
                int start = bstar ? P[bstar - 1] : 0;
                int end = P[bstar];
                double pref = bstar ? S[bstar - 1] : 0.0;
                int cin = 0;
                for (int q = start + lane; q < end; q += 32) {
                    float p = pval[q];
                    int id = lst[q];
                    double sb = 0.0;
                    for (int r = start; r < end; r++) {
                        float pr = pval[r];
                        int ir = lst[r];
                        if (pr > p || (pr == p && ir <= id)) sb += (double)pr;
                    }
                    if (pref + sb <= TOPPD) cin++;
                }
                for (int o = 16; o; o >>= 1) cin += __shfl_xor_sync(0xffffffffu, cin, o);
                count = start + cin;
            }
            if (lane == 0) {
                int k = count + 1;
                if (k > N_IMG) k = N_IMG;
                ictl[1] = k;
            }
        }
        __syncthreads();
        int k = ictl[1];

        // ---- keep: wholesale by bucket; exact only in straddling bucket ----
#pragma unroll
        for (int j = 0; j < CE; j++) {
            if (j < nmine) {
                float p = pv[j];
                int i = s0 + j;
                int bd = BUCKET(p);
                int start = bd ? P[bd - 1] : 0;
                int end = P[bd];
                unsigned char kp;
                if (end <= k) kp = 1;
                else if (start >= k) kp = 0;
                else {
                    int r = 0;
                    for (int q = start; q < end; q++) {
                        float pr = pval[q];
                        int ir = lst[q];
                        if (pr > p || (pr == p && ir < i)) r++;
                    }
                    kp = (start + r < k) ? 1 : 0;
                }
                g_keep[i] = kp;
            }
        }
#undef BUCKET
    }
    grid_bar(gen);

    // ========== E: zero dropped rows =======================================
    {
        float4 z = make_float4(0.f, 0.f, 0.f, 0.f);
        for (int r = b; r < N_IMG; r += NBLK) {
            if (!g_keep[r])
                ((float4*)(out + (size_t)r * DIM))[tid] = z;
        }
    }
}

// ---------------------------------------------------------------------------
extern "C" void kernel_launch(void* const* d_in, const int* in_sizes, int n_in,
                              void* d_out, int out_size) {
    const float*         lf   = (const float*)d_in[0];
    const float*         emb  = (const float*)d_in[1];
    const unsigned char* mask = (const unsigned char*)d_in[2];
    const float*         gn   = (const float*)d_in[3];
    float*               out  = (float*)d_out;

    cudaFuncSetAttribute(k_mega, cudaFuncAttributeMaxDynamicSharedMemorySize, SMEM3);
    k_mega<<<NBLK, NTH, SMEM3>>>(lf, emb, mask, gn, out);
}

// round 17
// speedup vs baseline: 1.0696x; 1.0696x over previous
#include <cuda_runtime.h>
#include <math.h>
#include <stdint.h>

#define N_IMG 4608
#define N_TXT 128
#define DIM   4096
#define NB    4096
#define NTH   1024
#define NBLK  148
#define CE    5          // elements per thread in topp block (ceil(4608/1024))

#define TOTF4 (N_IMG * (DIM / 4))   // 4718592 float4 elements
#define A_END 393216                // copied in phase A (~6.3MB read)
#define B_END 786432                // copied in phase B

// ---- scratch (no allocations allowed) ----
__device__ float g_v[DIM];
__device__ float g_invn[N_TXT];
__device__ float g_sim[N_IMG];
__device__ unsigned char g_keep[N_IMG];
__device__ unsigned int g_cnt = 0;
__device__ volatile unsigned int g_gen = 0;

// All NBLK blocks resident (1 CTA/SM, grid == 148 <= SM count): spin barrier
// is safe. Counting barrier with generation; g_cnt self-resets, g_gen grows
// monotonically across graph replays (each launch reads its start gen).
__device__ __forceinline__ void grid_bar(unsigned int& gen) {
    __syncthreads();
    if (threadIdx.x == 0) {
        __threadfence();
        unsigned int arrived = atomicAdd(&g_cnt, 1);
        if (arrived == NBLK - 1) {
            g_cnt = 0;
            __threadfence();
            g_gen = gen + 1;
        } else {
            while (g_gen == gen) { }
        }
        __threadfence();
    }
    __syncthreads();
    gen++;
}

// 8-deep batched copy, NO predication in the hot loop: 8 unpredicated LDG.128
// front-batched, then 8 streaming stores. Tail handled scalar. __stcs keeps
// `out` from evicting lf in L2.
__device__ __forceinline__ void copy_range8(const float4* __restrict__ src,
                                            float4* __restrict__ dst,
                                            int lo, int hi, int tg, int nth) {
    int i = lo + tg;
    const int step = 8 * nth;
    for (; i + 7 * nth < hi; i += step) {
        float4 a0 = __ldg(src + i);
        float4 a1 = __ldg(src + i + nth);
        float4 a2 = __ldg(src + i + 2 * nth);
        float4 a3 = __ldg(src + i + 3 * nth);
        float4 a4 = __ldg(src + i + 4 * nth);
        float4 a5 = __ldg(src + i + 5 * nth);
        float4 a6 = __ldg(src + i + 6 * nth);
        float4 a7 = __ldg(src + i + 7 * nth);
        __stcs(dst + i,           a0);
        __stcs(dst + i + nth,     a1);
        __stcs(dst + i + 2 * nth, a2);
        __stcs(dst + i + 3 * nth, a3);
        __stcs(dst + i + 4 * nth, a4);
        __stcs(dst + i + 5 * nth, a5);
        __stcs(dst + i + 6 * nth, a6);
        __stcs(dst + i + 7 * nth, a7);
    }
    for (; i < hi; i += nth)
        __stcs(dst + i, __ldg(src + i));
}

// ---------------------------------------------------------------------------
// Mega-kernel. Shared layout (bytes), used only by block 0's top-p phase:
//   pval : [0,     18432)   lst : [18432, 36864)
//   P    : [36864, 53248)   S   : [53248, 86016)
//   daux : [86016, 86272)   iaux: [86272, 86400)
//   red  : [86400, 86656)   ictl: [86656, 86664)
// ---------------------------------------------------------------------------
#define SMEM3 86720

__global__ void __launch_bounds__(NTH, 1)
k_mega(const float* __restrict__ lf,
       const float* __restrict__ emb,
       const unsigned char* __restrict__ maskb,
       const float* __restrict__ gnoise,
       float* __restrict__ out) {
    extern __shared__ unsigned char sraw[];
    float*  pval = (float*)(sraw);
    int*    lst  = (int*)(sraw + 18432);
    int*    P    = (int*)(sraw + 36864);
    double* S    = (double*)(sraw + 53248);
    double* daux = (double*)(sraw + 86016);
    int*    iaux = (int*)(sraw + 86272);
    float*  red  = (float*)(sraw + 86400);
    int*    ictl = (int*)(sraw + 86656);

    const int b    = blockIdx.x;
    const int tid  = threadIdx.x;
    const int lane = tid & 31;
    const int w    = tid >> 5;

    unsigned int gen = g_gen;

    const float4* srcf4 = (const float4*)lf;
    float4* dstf4 = (float4*)out;

    float val[CE];
    float pv[CE];
    float gn[CE];
    const int s0 = tid * CE;
    const int nmine = min(CE, max(0, N_IMG - s0));

    // ========== A: textnorm (blocks 0..3) || copy [0, A_END) ===============
    if (b < 4) {
        int t = b * 32 + w;                       // 0..127
        const float4* row = (const float4*)(emb + (size_t)t * DIM);
        float ss = 0.f;
#pragma unroll 8
        for (int k = 0; k < 32; k++) {
            float4 a = row[k * 32 + lane];
            ss += a.x * a.x + a.y * a.y + a.z * a.z + a.w * a.w;
        }
        for (int o = 16; o; o >>= 1) ss += __shfl_xor_sync(0xffffffffu, ss, o);
        // bool-layout probe: u8 layout has nonzero bytes at j%4!=0 in first
        // 128 bytes; i32 layout has flags only in byte 0 of each word.
        unsigned word = ((const unsigned*)maskb)[lane];
        bool isU8 = __ballot_sync(0xffffffffu, (word & 0xFFFFFF00u) != 0) != 0;
        if (lane == 0) {
            bool mv = isU8 ? (maskb[t] != 0) : (((const int*)maskb)[t] != 0);
            float n = fmaxf(sqrtf(ss), 1e-8f);
            g_invn[t] = mv ? (1.f / n) : 0.f;
        }
    } else {
        copy_range8(srcf4, dstf4, 0, A_END, (b - 4) * NTH + tid, 144 * NTH);
    }
    grid_bar(gen);

    // ========== B: buildv (1..4) || blk0 prologue || copy [A_END,B_END) ====
    if (b >= 1 && b <= 4) {
        int d = (b - 1) * NTH + tid;              // 0..4095
        float acc = 0.f;
#pragma unroll 8
        for (int t = 0; t < N_TXT; t++)
            acc = fmaf(emb[(size_t)t * DIM + d], g_invn[t], acc);
        g_v[d] = acc;
    } else if (b == 0) {
        for (int bb = tid; bb < NB; bb += NTH) { P[bb] = 0; S[bb] = 0.0; }
        if (tid == 0) ictl[0] = NB;
#pragma unroll
        for (int j = 0; j < CE; j++)
            if (j < nmine) gn[j] = gnoise[s0 + j];
    } else {
        copy_range8(srcf4, dstf4, A_END, B_END, (b - 5) * NTH + tid, 143 * NTH);
    }
    grid_bar(gen);

    // ========== C: sims (warp-per-row, shuffle-only) =======================
    {
        int r = b * 32 + w;                       // 0..4735
        if (r < N_IMG) {
            const float4* row = (const float4*)(lf + (size_t)r * DIM);
            const float4* v4  = (const float4*)g_v;
            float dot = 0.f, ss = 0.f;
#pragma unroll 8
            for (int k = 0; k < 32; k++) {
                float4 a = row[k * 32 + lane];
                float4 vv = v4[k * 32 + lane];
                dot += a.x * vv.x + a.y * vv.y + a.z * vv.z + a.w * vv.w;
                ss  += a.x * a.x + a.y * a.y + a.z * a.z + a.w * a.w;
            }
            for (int o = 16; o; o >>= 1) {
                dot += __shfl_xor_sync(0xffffffffu, dot, o);
                ss  += __shfl_xor_sync(0xffffffffu, ss, o);
            }
            if (lane == 0) {
                float n = fmaxf(sqrtf(ss), 1e-8f);
                g_sim[r] = dot / n;
            }
        }
    }
    grid_bar(gen);

    // ========== D: block 0 top-p || blocks 1..147 copy [B_END, TOTF4) ======
    if (b != 0) {
        copy_range8(srcf4, dstf4, B_END, TOTF4, (b - 1) * NTH + tid, 147 * NTH);
    } else {
        // ---- pass 1: t = 2*sim, max -> m1 ----
        float lm = -INFINITY;
#pragma unroll
        for (int j = 0; j < CE; j++) {
            if (j < nmine) {
                float t = 2.f * g_sim[s0 + j];
                val[j] = t;
                lm = fmaxf(lm, t);
            }
        }
        for (int o = 16; o; o >>= 1) lm = fmaxf(lm, __shfl_xor_sync(0xffffffffu, lm, o));
        if (lane == 0) red[w] = lm;
        __syncthreads();
        if (tid < 32) {
            float x = red[tid];
            for (int o = 16; o; o >>= 1) x = fmaxf(x, __shfl_xor_sync(0xffffffffu, x, o));
            if (tid == 0) red[0] = x;
        }
        __syncthreads();
        float m1 = red[0];
        __syncthreads();

        // ---- pass 2: e = exp(t - m1), sum -> Z1 ----
        float lsum = 0.f;
#pragma unroll
        for (int j = 0; j < CE; j++) {
            if (j < nmine) {
                float e = expf(val[j] - m1);
                val[j] = e;
                lsum += e;
            }
        }
        for (int o = 16; o; o >>= 1) lsum += __shfl_xor_sync(0xffffffffu, lsum, o);
        if (lane == 0) red[w] = lsum;
        __syncthreads();
        if (tid < 32) {
            float x = red[tid];
            for (int o = 16; o; o >>= 1) x += __shfl_xor_sync(0xffffffffu, x, o);
            if (tid == 0) red[0] = x;
        }
        __syncthreads();
        float Z1 = red[0];
        float r1 = 1.f / Z1;
        __syncthreads();

        // ---- pass 3: z = e/Z1 + g, max -> m2 ----
        float lm2 = -INFINITY;
#pragma unroll
        for (int j = 0; j < CE; j++) {
            if (j < nmine) {
                float z = val[j] * r1 + gn[j];
                val[j] = z;
                lm2 = fmaxf(lm2, z);
            }
        }
        for (int o = 16; o; o >>= 1) lm2 = fmaxf(lm2, __shfl_xor_sync(0xffffffffu, lm2, o));
        if (lane == 0) red[w] = lm2;
        __syncthreads();
        if (tid < 32) {
            float x = red[tid];
            for (int o = 16; o; o >>= 1) x = fmaxf(x, __shfl_xor_sync(0xffffffffu, x, o));
            if (tid == 0) red[0] = x;
        }
        __syncthreads();
        float m2 = red[0];
        __syncthreads();

        // ---- pass 4: e2 = exp(z - m2); sum + min/max in one reduction ----
        float ls2 = 0.f, emin = INFINITY, emax = -INFINITY;
#pragma unroll
        for (int j = 0; j < CE; j++) {
            if (j < nmine) {
                float e = expf(val[j] - m2);
                val[j] = e;
                ls2 += e;
                emin = fminf(emin, e);
                emax = fmaxf(emax, e);
            }
        }
        for (int o = 16; o; o >>= 1) {
            ls2  += __shfl_xor_sync(0xffffffffu, ls2, o);
            emin  = fminf(emin, __shfl_xor_sync(0xffffffffu, emin, o));
            emax  = fmaxf(emax, __shfl_xor_sync(0xffffffffu, emax, o));
        }
        if (lane == 0) { red[w] = ls2; red[32 + w] = emin; daux[w] = (double)emax; }
        __syncthreads();
        if (tid < 32) {
            float a = red[tid];
            float bb = red[32 + tid];
            float c = (float)daux[tid];
            for (int o = 16; o; o >>= 1) {
                a += __shfl_xor_sync(0xffffffffu, a, o);
                bb = fminf(bb, __shfl_xor_sync(0xffffffffu, bb, o));
                c  = fmaxf(c, __shfl_xor_sync(0xffffffffu, c, o));
            }
            if (tid == 0) { red[0] = a; red[1] = bb; red[2] = c; }
        }
        __syncthreads();
        float Z2 = red[0];
        float pmin = red[1] / Z2;   // p=f32(e2/Z2) monotone in e2 -> exact
        float pmax = red[2] / Z2;
        float scale = (float)(NB - 1) / fmaxf(pmax - pmin, 1e-30f);
        __syncthreads();

#define BUCKET(p) min(max((int)((pmax - (p)) * scale), 0), NB - 1)

        // ---- p = e2/Z2 (exact div); count + double sum per bucket ----
#pragma unroll
        for (int j = 0; j < CE; j++) {
            if (j < nmine) {
                float p = val[j] / Z2;
                pv[j] = p;
                int bd = BUCKET(p);
                atomicAdd(&P[bd], 1);
                atomicAdd(&S[bd], (double)p);
            }
        }
        __syncthreads();

        // ---- fused scans: P -> excl starts, S -> incl double prefix ----
        const int CB = NB / NTH;  // 4
        int base = tid * CB;
        int run = 0; double drun = 0.0;
#pragma unroll
        for (int j = 0; j < CB; j++) {
            int t = P[base + j];
            P[base + j] = run;
            run += t;
            drun += S[base + j];
            S[base + j] = drun;
        }
        int iv = run; double dvv = drun;
        for (int o = 1; o < 32; o <<= 1) {
            int ti = __shfl_up_sync(0xffffffffu, iv, o);
            double td = __shfl_up_sync(0xffffffffu, dvv, o);
            if (lane >= o) { iv += ti; dvv += td; }
        }
        if (lane == 31) { iaux[w] = iv; daux[w] = dvv; }
        __syncthreads();
        if (tid < 32) {
            int x = iaux[tid]; double y = daux[tid];
            for (int o = 1; o < 32; o <<= 1) {
                int ti = __shfl_up_sync(0xffffffffu, x, o);
                double td = __shfl_up_sync(0xffffffffu, y, o);
                if (tid >= o) { x += ti; y += td; }
            }
            iaux[tid] = x; daux[tid] = y;
        }
        __syncthreads();
        int iexcl = (iv - run) + (w ? iaux[w - 1] : 0);
        double dexcl = (dvv - drun) + (w ? daux[w - 1] : 0.0);
        if (iexcl) {
#pragma unroll
            for (int j = 0; j < CB; j++) P[base + j] += iexcl;
        }
        if (dexcl != 0.0) {
#pragma unroll
            for (int j = 0; j < CB; j++) S[base + j] += dexcl;
        }
        __syncthreads();

        // ---- scatter (p, id) by bucket; P becomes bucket ends ----
#pragma unroll
        for (int j = 0; j < CE; j++) {
            if (j < nmine) {
                int bd = BUCKET(pv[j]);
                int pos = atomicAdd(&P[bd], 1);
                lst[pos] = s0 + j;
                pval[pos] = pv[j];
            }
        }
        __syncthreads();

        const double TOPPD = (double)0.9f;  // jax promotes 0.9 -> f32

        // ---- find crossing bucket b*: S[b*] > 0.9 >= S[b*-1] ----
#pragma unroll
        for (int j = 0; j < CB; j++) {
            int bb = base + j;
            double incl = S[bb];
            double prev = bb ? S[bb - 1] : 0.0;
            if (incl > TOPPD && prev <= TOPPD) atomicMin(&ictl[0], bb);
        }
        __syncthreads();
        int bstar = ictl[0];

        // ---- warp 0: resolve crossing bucket exactly -> count, k ----
        if (w == 0) {
            int count;
            if (bstar >= NB) {
                count = N_IMG;
            } else {
                int start = bstar ? P[bstar - 1] : 0;
                int end = P[bstar];
                double pref = bstar ? S[bstar - 1] : 0.0;
                int cin = 0;
                for (int q = start + lane; q < end; q += 32) {
                    float p = pval[q];
                    int id = lst[q];
                    double sb = 0.0;
                    for (int r = start; r < end; r++) {
                        float pr = pval[r];
                        int ir = lst[r];
                        if (pr > p || (pr == p && ir <= id)) sb += (double)pr;
                    }
                    if (pref + sb <= TOPPD) cin++;
                }
                for (int o = 16; o; o >>= 1) cin += __shfl_xor_sync(0xffffffffu, cin, o);
                count = start + cin;
            }
            if (lane == 0) {
                int k = count + 1;
                if (k > N_IMG) k = N_IMG;
                ictl[1] = k;
            }
        }
        __syncthreads();
        int k = ictl[1];

        // ---- keep: wholesale by bucket; exact only in straddling bucket ----
#pragma unroll
        for (int j = 0; j < CE; j++) {
            if (j < nmine) {
                float p = pv[j];
                int i = s0 + j;
                int bd = BUCKET(p);
                int start = bd ? P[bd - 1] : 0;
                int end = P[bd];
                unsigned char kp;
                if (end <= k) kp = 1;
                else if (start >= k) kp = 0;
                else {
                    int r = 0;
                    for (int q = start; q < end; q++) {
                        float pr = pval[q];
                        int ir = lst[q];
                        if (pr > p || (pr == p && ir < i)) r++;
                    }
                    kp = (start + r < k) ? 1 : 0;
                }
                g_keep[i] = kp;
            }
        }
#undef BUCKET
    }
    grid_bar(gen);

    // ========== E: zero dropped rows (streaming stores) ====================
    {
        float4 z = make_float4(0.f, 0.f, 0.f, 0.f);
        for (int r = b; r < N_IMG; r += NBLK) {
            if (!g_keep[r])
                __stcs(((float4*)(out + (size_t)r * DIM)) + tid, z);
        }
    }
}

// ---------------------------------------------------------------------------
extern "C" void kernel_launch(void* const* d_in, const int* in_sizes, int n_in,
                              void* d_out, int out_size) {
    const float*         lf   = (const float*)d_in[0];
    const float*         emb  = (const float*)d_in[1];
    const unsigned char* mask = (const unsigned char*)d_in[2];
    const float*         gn   = (const float*)d_in[3];
    float*               out  = (float*)d_out;

    cudaFuncSetAttribute(k_mega, cudaFuncAttributeMaxDynamicSharedMemorySize, SMEM3);
    k_mega<<<NBLK, NTH, SMEM3>>>(lf, emb, mask, gn, out);
}